// round 1
// baseline (speedup 1.0000x reference)
#include <cuda_runtime.h>

#define NN 100000   // nodes
#define NE 800000   // edges
#define C  100      // feature width (IN = HID = concat of two 50-wide heads)
#define OC 50       // out channels per head
#define TM 64       // gemm row tile
#define KC 20       // gemm k chunk

// Scratch (device globals — no allocation allowed)
__device__ __align__(16) float d_dis[NN];        // deg -> deg^-1/2
__device__ __align__(16) float d_G[NN * C];      // g = (A @ W) * dis[row]
__device__ __align__(16) float d_AGG[NN * C];    // g[i] + sum_{src->i} g[src]
__device__ __align__(16) float d_H[NN * C];      // hidden activations

__global__ void k_zero_deg() {
    int i = blockIdx.x * blockDim.x + threadIdx.x;
    if (i < NN) d_dis[i] = 0.f;
}

__global__ void k_deg(const int* __restrict__ dst) {
    int e = blockIdx.x * blockDim.x + threadIdx.x;
    if (e < NE) atomicAdd(&d_dis[dst[e]], 1.0f);
}

__global__ void k_deg_fin() {
    int i = blockIdx.x * blockDim.x + threadIdx.x;
    if (i < NN) d_dis[i] = rsqrtf(d_dis[i] + 1.0f);
}

// G[i,:] = AGG[i,:] = dis[i] * (A[i,:] @ W)
// mode 0: A = Ain, W = W0 [C x C]
// mode 1: A = d_H, W = [Wa | Wb] column-concat ([C x OC] each)
__global__ __launch_bounds__(400) void k_gemm(const float* __restrict__ Ain,
                                              const float* __restrict__ W0,
                                              const float* __restrict__ Wa,
                                              const float* __restrict__ Wb,
                                              int mode) {
    __shared__ float xs[TM][KC + 1];
    __shared__ float ws[KC][C];
    const float* A = (mode == 0) ? Ain : d_H;
    const int tid = threadIdx.x;
    const int cx = tid % 25;   // column quad: cols [4*cx, 4*cx+3]
    const int ry = tid / 25;   // row quad: rows [4*ry, 4*ry+3] (0..15)
    const int i0 = blockIdx.x * TM;

    float acc[4][4] = {};

    for (int kb = 0; kb < C; kb += KC) {
        // stage A tile [TM x KC]
        for (int t = tid; t < TM * KC; t += 400) {
            int r = t / KC, k = t % KC;
            int row = i0 + r;
            xs[r][k] = (row < NN) ? A[row * C + kb + k] : 0.f;
        }
        // stage W chunk [KC x C]
        for (int t = tid; t < KC * C; t += 400) {
            int kk = t / C, c = t % C;
            int kg = kb + kk;
            float w;
            if (mode == 0) w = W0[kg * C + c];
            else           w = (c < OC) ? Wa[kg * OC + c] : Wb[kg * OC + (c - OC)];
            ws[kk][c] = w;
        }
        __syncthreads();

        #pragma unroll
        for (int kk = 0; kk < KC; kk++) {
            float4 wv = *(const float4*)&ws[kk][cx * 4];
            #pragma unroll
            for (int rr = 0; rr < 4; rr++) {
                float xv = xs[ry * 4 + rr][kk];
                acc[rr][0] += xv * wv.x;
                acc[rr][1] += xv * wv.y;
                acc[rr][2] += xv * wv.z;
                acc[rr][3] += xv * wv.w;
            }
        }
        __syncthreads();
    }

    #pragma unroll
    for (int rr = 0; rr < 4; rr++) {
        int row = i0 + ry * 4 + rr;
        if (row < NN) {
            float s = d_dis[row];
            float4 v = make_float4(acc[rr][0] * s, acc[rr][1] * s,
                                   acc[rr][2] * s, acc[rr][3] * s);
            *(float4*)&d_G[row * C + cx * 4]   = v;  // gather source
            *(float4*)&d_AGG[row * C + cx * 4] = v;  // init accum = self-loop term
        }
    }
}

// AGG[dst,:] += G[src,:]   (25 threads of 1 float4 each per edge)
__global__ void k_scatter(const int* __restrict__ src, const int* __restrict__ dst) {
    int t = blockIdx.x * blockDim.x + threadIdx.x;
    int e = t / 25;
    if (e >= NE) return;
    int p = t % 25;
    int s = src[e], d = dst[e];
    float4 g = *(const float4*)&d_G[s * C + p * 4];
    float* o = &d_AGG[d * C + p * 4];
    atomicAdd(o + 0, g.x);   // no return -> RED.E.ADD.F32
    atomicAdd(o + 1, g.y);
    atomicAdd(o + 2, g.z);
    atomicAdd(o + 3, g.w);
}

// H = relu(dis[i] * AGG + b1)
__global__ void k_relu(const float* __restrict__ b) {
    int t = blockIdx.x * blockDim.x + threadIdx.x;
    if (t >= NN * 25) return;
    int i = t / 25, p = t % 25;
    float s = d_dis[i];
    float4 a  = *(const float4*)&d_AGG[i * C + p * 4];
    float4 bb = *(const float4*)&b[p * 4];
    float4 h;
    h.x = fmaxf(fmaf(s, a.x, bb.x), 0.f);
    h.y = fmaxf(fmaf(s, a.y, bb.y), 0.f);
    h.z = fmaxf(fmaf(s, a.z, bb.z), 0.f);
    h.w = fmaxf(fmaf(s, a.w, bb.w), 0.f);
    *(float4*)&d_H[i * C + p * 4] = h;
}

// out = [mu (N x 50) | logstd (N x 50)]
__global__ void k_out(const float* __restrict__ bmu, const float* __restrict__ bls,
                      float* __restrict__ out) {
    int t = blockIdx.x * blockDim.x + threadIdx.x;
    if (t >= NN * C) return;
    int i = t / C, c = t % C;
    float v = d_dis[i] * d_AGG[t];
    if (c < OC) out[i * OC + c]                 = v + bmu[c];
    else        out[NN * OC + i * OC + (c - OC)] = v + bls[c - OC];
}

extern "C" void kernel_launch(void* const* d_in, const int* in_sizes, int n_in,
                              void* d_out, int out_size) {
    const float* x   = (const float*)d_in[0];
    const int*   ei  = (const int*)  d_in[1];
    const float* W1  = (const float*)d_in[2];
    const float* b1  = (const float*)d_in[3];
    const float* Wmu = (const float*)d_in[4];
    const float* bmu = (const float*)d_in[5];
    const float* Wls = (const float*)d_in[6];
    const float* bls = (const float*)d_in[7];
    float* out = (float*)d_out;

    const int* src = ei;        // edge_index[0]
    const int* dst = ei + NE;   // edge_index[1]

    k_zero_deg<<<(NN + 255) / 256, 256>>>();
    k_deg<<<(NE + 255) / 256, 256>>>(dst);
    k_deg_fin<<<(NN + 255) / 256, 256>>>();

    // layer 1
    k_gemm<<<(NN + TM - 1) / TM, 400>>>(x, W1, nullptr, nullptr, 0);
    k_scatter<<<(NE * 25 + 255) / 256, 256>>>(src, dst);
    k_relu<<<(NN * 25 + 255) / 256, 256>>>(b1);

    // layers 2+3 fused (mu | logstd column-concat)
    k_gemm<<<(NN + TM - 1) / TM, 400>>>(nullptr, nullptr, Wmu, Wls, 1);
    k_scatter<<<(NE * 25 + 255) / 256, 256>>>(src, dst);
    k_out<<<(NN * C + 255) / 256, 256>>>(bmu, bls, out);
}

// round 2
// speedup vs baseline: 1.6771x; 1.6771x over previous
#include <cuda_runtime.h>

#define NN 100000   // nodes
#define NE 800000   // edges
#define C  100      // feature width
#define OC 50       // out channels per head
#define TM 128      // gemm row tile
#define KC 20       // gemm k chunk
#define NBLK ((NN + 1023) / 1024)

// Scratch (device globals — no allocation allowed)
__device__ __align__(16) float d_dis[NN];        // deg^-1/2
__device__ __align__(16) float d_G[NN * C];      // g = (A @ W) * dis[row]
__device__ __align__(16) float d_H[NN * C];      // hidden activations
__device__ int d_cnt[NN];                        // in-degree counts
__device__ int d_start[NN];                      // CSR row starts (exclusive scan)
__device__ int d_fill[NN];                       // fill cursors
__device__ int d_csr[NE];                        // src lists bucketed by dst
__device__ int d_bsum[NBLK + 1];
__device__ int d_boff[NBLK + 1];

__global__ void k_zero() {
    int i = blockIdx.x * blockDim.x + threadIdx.x;
    if (i < NN) { d_cnt[i] = 0; d_fill[i] = 0; }
}

__global__ void k_deg(const int* __restrict__ dst) {
    int e = blockIdx.x * blockDim.x + threadIdx.x;
    if (e < NE) atomicAdd(&d_cnt[dst[e]], 1);
}

__global__ void k_deg_fin() {
    int i = blockIdx.x * blockDim.x + threadIdx.x;
    if (i < NN) d_dis[i] = rsqrtf((float)d_cnt[i] + 1.0f);
}

__global__ void k_scan1() {
    __shared__ int sh[1024];
    int i = blockIdx.x * 1024 + threadIdx.x;
    int v = (i < NN) ? d_cnt[i] : 0;
    sh[threadIdx.x] = v;
    __syncthreads();
    for (int off = 1; off < 1024; off <<= 1) {
        int t = (threadIdx.x >= off) ? sh[threadIdx.x - off] : 0;
        __syncthreads();
        sh[threadIdx.x] += t;
        __syncthreads();
    }
    if (i < NN) d_start[i] = sh[threadIdx.x] - v;   // exclusive within block
    if (threadIdx.x == 1023) d_bsum[blockIdx.x] = sh[1023];
}

__global__ void k_scan2() {
    if (threadIdx.x == 0) {
        int run = 0;
        for (int b = 0; b < NBLK; b++) { d_boff[b] = run; run += d_bsum[b]; }
    }
}

__global__ void k_scan3() {
    int i = blockIdx.x * blockDim.x + threadIdx.x;
    if (i < NN) d_start[i] += d_boff[i >> 10];
}

__global__ void k_fill(const int* __restrict__ src, const int* __restrict__ dst) {
    int e = blockIdx.x * blockDim.x + threadIdx.x;
    if (e >= NE) return;
    int d = dst[e];
    int p = atomicAdd(&d_fill[d], 1);
    d_csr[d_start[d] + p] = src[e];
}

// G[i,:] = dis[i] * (A[i,:] @ W)
// mode 0: A = Ain, W = W0 [C x C];  mode 1: A = d_H, W = [Wa | Wb] concat
__global__ __launch_bounds__(400) void k_gemm(const float* __restrict__ Ain,
                                              const float* __restrict__ W0,
                                              const float* __restrict__ Wa,
                                              const float* __restrict__ Wb,
                                              int mode) {
    __shared__ float xs[TM][KC + 1];
    __shared__ float ws[KC][C];
    const float* A = (mode == 0) ? Ain : d_H;
    const int tid = threadIdx.x;
    const int cx = tid % 25;   // cols [4*cx, 4*cx+3]
    const int ry = tid / 25;   // rows [8*ry, 8*ry+7] (0..15)
    const int i0 = blockIdx.x * TM;

    float acc[8][4] = {};

    for (int kb = 0; kb < C; kb += KC) {
        for (int t = tid; t < TM * KC; t += 400) {
            int r = t / KC, k = t % KC;
            int row = i0 + r;
            xs[r][k] = (row < NN) ? A[row * C + kb + k] : 0.f;
        }
        for (int t = tid; t < KC * C; t += 400) {
            int kk = t / C, c = t % C;
            int kg = kb + kk;
            float w;
            if (mode == 0) w = W0[kg * C + c];
            else           w = (c < OC) ? Wa[kg * OC + c] : Wb[kg * OC + (c - OC)];
            ws[kk][c] = w;
        }
        __syncthreads();

        #pragma unroll
        for (int kk = 0; kk < KC; kk++) {
            float4 wv = *(const float4*)&ws[kk][cx * 4];
            float xv[8];
            #pragma unroll
            for (int rr = 0; rr < 8; rr++) xv[rr] = xs[ry * 8 + rr][kk];
            #pragma unroll
            for (int rr = 0; rr < 8; rr++) {
                acc[rr][0] += xv[rr] * wv.x;
                acc[rr][1] += xv[rr] * wv.y;
                acc[rr][2] += xv[rr] * wv.z;
                acc[rr][3] += xv[rr] * wv.w;
            }
        }
        __syncthreads();
    }

    #pragma unroll
    for (int rr = 0; rr < 8; rr++) {
        int row = i0 + ry * 8 + rr;
        if (row < NN) {
            float s = d_dis[row];
            float4 v = make_float4(acc[rr][0] * s, acc[rr][1] * s,
                                   acc[rr][2] * s, acc[rr][3] * s);
            *(float4*)&d_G[row * C + cx * 4] = v;
        }
    }
}

// One warp per node: sum = G[i,:] + sum_{src in csr[i]} G[src,:], then epilogue.
// mode 0: H = relu(dis[i]*sum + b1)
// mode 1: out = [dis[i]*sum[:50]+bmu | dis[i]*sum[50:]+bls] split-written
__global__ void k_gather(int mode, const float* __restrict__ b1,
                         const float* __restrict__ bmu, const float* __restrict__ bls,
                         float* __restrict__ out) {
    int w = (blockIdx.x * blockDim.x + threadIdx.x) >> 5;
    int lane = threadIdx.x & 31;
    if (w >= NN || lane >= 25) return;
    int st = d_start[w], n = d_cnt[w];
    int p4 = lane * 4;

    float4 acc = *(const float4*)&d_G[w * C + p4];      // self-loop term
    for (int j = 0; j < n; j++) {
        int s = d_csr[st + j];                          // broadcast load
        float4 g = *(const float4*)&d_G[s * C + p4];
        acc.x += g.x; acc.y += g.y; acc.z += g.z; acc.w += g.w;
    }
    float sc = d_dis[w];

    if (mode == 0) {
        float4 bb = *(const float4*)&b1[p4];
        float4 h;
        h.x = fmaxf(fmaf(sc, acc.x, bb.x), 0.f);
        h.y = fmaxf(fmaf(sc, acc.y, bb.y), 0.f);
        h.z = fmaxf(fmaf(sc, acc.z, bb.z), 0.f);
        h.w = fmaxf(fmaf(sc, acc.w, bb.w), 0.f);
        *(float4*)&d_H[w * C + p4] = h;
    } else {
        float v[4] = { sc * acc.x, sc * acc.y, sc * acc.z, sc * acc.w };
        #pragma unroll
        for (int q = 0; q < 4; q++) {
            int c = p4 + q;
            if (c < OC) out[w * OC + c]                   = v[q] + bmu[c];
            else        out[NN * OC + w * OC + (c - OC)]  = v[q] + bls[c - OC];
        }
    }
}

extern "C" void kernel_launch(void* const* d_in, const int* in_sizes, int n_in,
                              void* d_out, int out_size) {
    const float* x   = (const float*)d_in[0];
    const int*   ei  = (const int*)  d_in[1];
    const float* W1  = (const float*)d_in[2];
    const float* b1  = (const float*)d_in[3];
    const float* Wmu = (const float*)d_in[4];
    const float* bmu = (const float*)d_in[5];
    const float* Wls = (const float*)d_in[6];
    const float* bls = (const float*)d_in[7];
    float* out = (float*)d_out;

    const int* src = ei;
    const int* dst = ei + NE;

    // CSR build (once, reused by both gathers)
    k_zero<<<(NN + 255) / 256, 256>>>();
    k_deg<<<(NE + 255) / 256, 256>>>(dst);
    k_deg_fin<<<(NN + 255) / 256, 256>>>();
    k_scan1<<<NBLK, 1024>>>();
    k_scan2<<<1, 32>>>();
    k_scan3<<<(NN + 255) / 256, 256>>>();
    k_fill<<<(NE + 255) / 256, 256>>>(src, dst);

    // layer 1
    k_gemm<<<(NN + TM - 1) / TM, 400>>>(x, W1, nullptr, nullptr, 0);
    k_gather<<<(NN * 32 + 255) / 256, 256>>>(0, b1, nullptr, nullptr, nullptr);

    // layers 2+3 fused (mu | logstd column-concat)
    k_gemm<<<(NN + TM - 1) / TM, 400>>>(nullptr, nullptr, Wmu, Wls, 1);
    k_gather<<<(NN * 32 + 255) / 256, 256>>>(1, nullptr, bmu, bls, out);
}

// round 4
// speedup vs baseline: 2.6010x; 1.5508x over previous
#include <cuda_runtime.h>
#include <stdint.h>

#define NN 100000
#define NE 800000
#define C  100
#define OC 50
#define NBLK ((NN + 1023) / 1024)

#define TM 128                 // gemm row tile
#define NTILES ((NN + TM - 1) / TM)
#define GEMM_GRID 148
#define GEMM_THREADS 256

// smem float offsets (stride-108 padding -> conflict-free frag loads)
#define AS 108
#define BS 108
#define AHI 0
#define ALO (128 * AS)             // 13824
#define BHI (2 * 128 * AS)         // 27648
#define BLO (BHI + 104 * BS)       // 38880
#define SM_FLOATS (BLO + 104 * BS) // 50112
#define SMEM_DYN (SM_FLOATS * 4)   // 200448 bytes

// ---------------- device globals (scratch) ----------------
__device__ __align__(16) float d_dis[NN];
__device__ __align__(16) float d_G[NN * C];
__device__ __align__(16) float d_H[NN * C];
__device__ int d_cnt[NN];
__device__ int d_start[NN];
__device__ int d_fill[NN];
__device__ int d_csr[NE];
__device__ int d_bsum[NBLK + 1];
__device__ int d_boff[NBLK + 1];

// ---------------- mma helpers (baseline PTX, sm_80+) ----------------
__device__ __forceinline__ uint32_t f2tf32(float x) {
    uint32_t r;
    asm("cvt.rna.tf32.f32 %0, %1;" : "=r"(r) : "f"(x));
    return r;
}
__device__ __forceinline__ void mma_tf32(float* d, const uint32_t* a, const uint32_t* b) {
    asm volatile(
        "mma.sync.aligned.m16n8k8.row.col.f32.tf32.tf32.f32 "
        "{%0,%1,%2,%3}, {%4,%5,%6,%7}, {%8,%9}, {%0,%1,%2,%3};"
        : "+f"(d[0]), "+f"(d[1]), "+f"(d[2]), "+f"(d[3])
        : "r"(a[0]), "r"(a[1]), "r"(a[2]), "r"(a[3]), "r"(b[0]), "r"(b[1]));
}

// ---------------- CSR build ----------------
__global__ void k_zero() {
    int i = blockIdx.x * blockDim.x + threadIdx.x;
    if (i < NN) { d_cnt[i] = 0; d_fill[i] = 0; }
}
__global__ void k_deg(const int* __restrict__ dst) {
    int e = blockIdx.x * blockDim.x + threadIdx.x;
    if (e < NE) atomicAdd(&d_cnt[dst[e]], 1);
}
__global__ void k_deg_fin() {
    int i = blockIdx.x * blockDim.x + threadIdx.x;
    if (i < NN) d_dis[i] = rsqrtf((float)d_cnt[i] + 1.0f);
}
__global__ void k_scan1() {
    __shared__ int sh[1024];
    int i = blockIdx.x * 1024 + threadIdx.x;
    int v = (i < NN) ? d_cnt[i] : 0;
    sh[threadIdx.x] = v;
    __syncthreads();
    for (int off = 1; off < 1024; off <<= 1) {
        int t = (threadIdx.x >= off) ? sh[threadIdx.x - off] : 0;
        __syncthreads();
        sh[threadIdx.x] += t;
        __syncthreads();
    }
    if (i < NN) d_start[i] = sh[threadIdx.x] - v;
    if (threadIdx.x == 1023) d_bsum[blockIdx.x] = sh[1023];
}
__global__ void k_scan2() {   // 128-thread scan over NBLK=98 partials
    __shared__ int sh[128];
    int t = threadIdx.x;
    int v = (t < NBLK) ? d_bsum[t] : 0;
    sh[t] = v;
    __syncthreads();
    for (int off = 1; off < 128; off <<= 1) {
        int u = (t >= off) ? sh[t - off] : 0;
        __syncthreads();
        sh[t] += u;
        __syncthreads();
    }
    if (t < NBLK) d_boff[t] = sh[t] - v;
}
__global__ void k_scan3() {
    int i = blockIdx.x * blockDim.x + threadIdx.x;
    if (i < NN) d_start[i] += d_boff[i >> 10];
}
__global__ void k_fill(const int* __restrict__ src, const int* __restrict__ dst) {
    int e = blockIdx.x * blockDim.x + threadIdx.x;
    if (e >= NE) return;
    int d = dst[e];
    int p = atomicAdd(&d_fill[d], 1);
    d_csr[d_start[d] + p] = src[e];
}

// ---------------- 3xTF32 tensor-core GEMM: G = dis[row] * (A @ W) ----------------
// mode 0: A = Ain, W = W0 [C x C]; mode 1: A = d_H, W = [Wa|Wb] column-concat.
__global__ void __launch_bounds__(GEMM_THREADS, 1)
k_gemm_tc(const float* __restrict__ Ain, const float* __restrict__ W0,
          const float* __restrict__ Wa, const float* __restrict__ Wb, int mode) {
    extern __shared__ uint32_t sm[];
    const float* A = (mode == 0) ? Ain : d_H;
    const int tid = threadIdx.x, wid = tid >> 5, lane = tid & 31;
    const int g = lane >> 2, tg = lane & 3;

    // zero all smem once (pads stay zero forever)
    for (int i = tid; i < SM_FLOATS; i += GEMM_THREADS) sm[i] = 0;
    __syncthreads();

    // stage W -> tf32 hi/lo, layout B[k][n] stride BS
    for (int idx = tid; idx < C * C; idx += GEMM_THREADS) {
        int k = idx / C, n = idx % C;
        float w = (mode == 0) ? W0[idx]
                              : ((n < OC) ? Wa[k * OC + n] : Wb[k * OC + (n - OC)]);
        uint32_t hi = f2tf32(w);
        uint32_t lo = f2tf32(w - __uint_as_float(hi));
        sm[BHI + k * BS + n] = hi;
        sm[BLO + k * BS + n] = lo;
    }
    __syncthreads();

    const int r0 = wid * 16;   // warp's 16-row slice within the tile

    for (int t = blockIdx.x; t < NTILES; t += gridDim.x) {
        const int i0 = t * TM;
        const int rowlim = NN - i0;

        // stage A tile [128 x 100] -> tf32 hi/lo, stride AS
        for (int q = tid; q < TM * 25; q += GEMM_THREADS) {
            int r = q / 25, c4 = (q % 25) * 4;
            float4 v = (r < rowlim) ? *(const float4*)&A[(size_t)(i0 + r) * C + c4]
                                    : make_float4(0.f, 0.f, 0.f, 0.f);
            uint32_t hx = f2tf32(v.x), hy = f2tf32(v.y), hz = f2tf32(v.z), hw = f2tf32(v.w);
            uint32_t base = r * AS + c4;
            sm[AHI + base + 0] = hx;
            sm[AHI + base + 1] = hy;
            sm[AHI + base + 2] = hz;
            sm[AHI + base + 3] = hw;
            sm[ALO + base + 0] = f2tf32(v.x - __uint_as_float(hx));
            sm[ALO + base + 1] = f2tf32(v.y - __uint_as_float(hy));
            sm[ALO + base + 2] = f2tf32(v.z - __uint_as_float(hz));
            sm[ALO + base + 3] = f2tf32(v.w - __uint_as_float(hw));
        }
        __syncthreads();

        float acc[13][4];
        #pragma unroll
        for (int nt = 0; nt < 13; nt++)
            #pragma unroll
            for (int q = 0; q < 4; q++) acc[nt][q] = 0.f;

        #pragma unroll
        for (int kt = 0; kt < 13; kt++) {
            const int k0 = kt * 8;
            uint32_t ah[4], al[4];
            ah[0] = sm[AHI + (r0 + g) * AS + k0 + tg];
            ah[1] = sm[AHI + (r0 + g + 8) * AS + k0 + tg];
            ah[2] = sm[AHI + (r0 + g) * AS + k0 + tg + 4];
            ah[3] = sm[AHI + (r0 + g + 8) * AS + k0 + tg + 4];
            al[0] = sm[ALO + (r0 + g) * AS + k0 + tg];
            al[1] = sm[ALO + (r0 + g + 8) * AS + k0 + tg];
            al[2] = sm[ALO + (r0 + g) * AS + k0 + tg + 4];
            al[3] = sm[ALO + (r0 + g + 8) * AS + k0 + tg + 4];
            #pragma unroll
            for (int nt = 0; nt < 13; nt++) {
                const int n0 = nt * 8;
                uint32_t bh[2], bl[2];
                bh[0] = sm[BHI + (k0 + tg) * BS + n0 + g];
                bh[1] = sm[BHI + (k0 + tg + 4) * BS + n0 + g];
                bl[0] = sm[BLO + (k0 + tg) * BS + n0 + g];
                bl[1] = sm[BLO + (k0 + tg + 4) * BS + n0 + g];
                mma_tf32(acc[nt], ah, bh);   // hi*hi
                mma_tf32(acc[nt], al, bh);   // lo*hi
                mma_tf32(acc[nt], ah, bl);   // hi*lo
            }
        }

        // epilogue: scale by dis[row], write d_G
        const int row1 = i0 + r0 + g, row2 = row1 + 8;
        const float s1 = (row1 < NN) ? d_dis[row1] : 0.f;
        const float s2 = (row2 < NN) ? d_dis[row2] : 0.f;
        #pragma unroll
        for (int nt = 0; nt < 13; nt++) {
            const int c = nt * 8 + 2 * tg;
            if (c < C) {
                if (row1 < NN)
                    *(float2*)&d_G[(size_t)row1 * C + c] =
                        make_float2(s1 * acc[nt][0], s1 * acc[nt][1]);
                if (row2 < NN)
                    *(float2*)&d_G[(size_t)row2 * C + c] =
                        make_float2(s2 * acc[nt][2], s2 * acc[nt][3]);
            }
        }
        __syncthreads();   // all reads of A smem done before next staging
    }
}

// ---------------- gather + epilogues ----------------
__global__ void k_gather(int mode, const float* __restrict__ b1,
                         const float* __restrict__ bmu, const float* __restrict__ bls,
                         float* __restrict__ out) {
    int w = (blockIdx.x * blockDim.x + threadIdx.x) >> 5;
    int lane = threadIdx.x & 31;
    if (w >= NN || lane >= 25) return;
    int st = d_start[w], n = d_cnt[w];
    int p4 = lane * 4;

    float4 acc = *(const float4*)&d_G[(size_t)w * C + p4];   // self-loop term
    for (int j = 0; j < n; j++) {
        int s = d_csr[st + j];
        float4 g = *(const float4*)&d_G[(size_t)s * C + p4];
        acc.x += g.x; acc.y += g.y; acc.z += g.z; acc.w += g.w;
    }
    float sc = d_dis[w];

    if (mode == 0) {
        float4 bb = *(const float4*)&b1[p4];
        float4 h;
        h.x = fmaxf(fmaf(sc, acc.x, bb.x), 0.f);
        h.y = fmaxf(fmaf(sc, acc.y, bb.y), 0.f);
        h.z = fmaxf(fmaf(sc, acc.z, bb.z), 0.f);
        h.w = fmaxf(fmaf(sc, acc.w, bb.w), 0.f);
        *(float4*)&d_H[(size_t)w * C + p4] = h;
    } else {
        float v[4] = { sc * acc.x, sc * acc.y, sc * acc.z, sc * acc.w };
        #pragma unroll
        for (int q = 0; q < 4; q++) {
            int c = p4 + q;
            if (c < OC) out[(size_t)w * OC + c]                          = v[q] + bmu[c];
            else        out[(size_t)NN * OC + (size_t)w * OC + (c - OC)] = v[q] + bls[c - OC];
        }
    }
}

extern "C" void kernel_launch(void* const* d_in, const int* in_sizes, int n_in,
                              void* d_out, int out_size) {
    const float* x   = (const float*)d_in[0];
    const int*   ei  = (const int*)  d_in[1];
    const float* W1  = (const float*)d_in[2];
    const float* b1  = (const float*)d_in[3];
    const float* Wmu = (const float*)d_in[4];
    const float* bmu = (const float*)d_in[5];
    const float* Wls = (const float*)d_in[6];
    const float* bls = (const float*)d_in[7];
    float* out = (float*)d_out;

    const int* src = ei;
    const int* dst = ei + NE;

    cudaFuncSetAttribute(k_gemm_tc, cudaFuncAttributeMaxDynamicSharedMemorySize, SMEM_DYN);

    // CSR build (once, reused by both gathers)
    k_zero<<<(NN + 255) / 256, 256>>>();
    k_deg<<<(NE + 255) / 256, 256>>>(dst);
    k_deg_fin<<<(NN + 255) / 256, 256>>>();
    k_scan1<<<NBLK, 1024>>>();
    k_scan2<<<1, 128>>>();
    k_scan3<<<(NN + 255) / 256, 256>>>();
    k_fill<<<(NE + 255) / 256, 256>>>(src, dst);

    // layer 1
    k_gemm_tc<<<GEMM_GRID, GEMM_THREADS, SMEM_DYN>>>(x, W1, nullptr, nullptr, 0);
    k_gather<<<(NN * 32 + 255) / 256, 256>>>(0, b1, nullptr, nullptr, nullptr);

    // layers 2+3 fused (mu | logstd column-concat)
    k_gemm_tc<<<GEMM_GRID, GEMM_THREADS, SMEM_DYN>>>(nullptr, nullptr, Wmu, Wls, 1);
    k_gather<<<(NN * 32 + 255) / 256, 256>>>(1, nullptr, bmu, bls, out);
}